// round 3
// baseline (speedup 1.0000x reference)
#include <cuda_runtime.h>
#include <cstdint>

#define N_GROUPS 262144
#define EMBED_DIM 64

// 16 lanes per group, 2 groups per warp, 8 groups per warp-iteration.
// Each lane covers dims [4*l, 4*l+4) via one float4 load per embedding row
// (16 lanes x 16B = fully coalesced 256B row fetch).
__global__ __launch_bounds__(256, 3)
void afm_kernel(const int*   __restrict__ group,
                const float* __restrict__ embed,
                const float* __restrict__ W1,
                const float* __restrict__ b1,
                const float* __restrict__ W2,
                const float* __restrict__ b2,
                const float* __restrict__ Wp,
                const float* __restrict__ bp,
                float*       __restrict__ out)
{
    const int lane = threadIdx.x & 31;
    const int sub  = lane >> 4;   // which of 2 groups in this warp
    const int l    = lane & 15;   // lane within the 16-lane subgroup

    const int warp_global = (blockIdx.x * blockDim.x + threadIdx.x) >> 5;
    const int nwarps      = (gridDim.x * blockDim.x) >> 5;

    // Per-lane W1 slice: rows (4*l+k), k=0..3; each row = 4 floats.
    float4 w1r[4];
#pragma unroll
    for (int k = 0; k < 4; k++)
        w1r[k] = *reinterpret_cast<const float4*>(W1 + (l * 4 + k) * 4);

    const float b10 = b1[0], b11 = b1[1], b12 = b1[2], b13 = b1[3];
    const float w20 = W2[0], w21 = W2[1], w22 = W2[2], w23 = W2[3];
    const float b2r = b2[0];
    const float wp0 = Wp[0], wp1 = Wp[1], wp2 = Wp[2];
    const float bpr = bp[0];

    for (int g0 = warp_global * 8; g0 < N_GROUPS; g0 += nwarps * 8) {
        // One coalesced load of 24 indices = 8 groups' worth for this warp.
        int v = 0;
        if (lane < 24) v = group[g0 * 3 + lane];

#pragma unroll
        for (int it = 0; it < 4; it++) {
            const int g  = g0 + it * 2 + sub;
            const int i0 = __shfl_sync(0xffffffffu, v, it * 6 + sub * 3 + 0);
            const int i1 = __shfl_sync(0xffffffffu, v, it * 6 + sub * 3 + 1);
            const int i2 = __shfl_sync(0xffffffffu, v, it * 6 + sub * 3 + 2);

            const float4 e0 = *reinterpret_cast<const float4*>(
                embed + (size_t)i0 * EMBED_DIM + l * 4);
            const float4 e1 = *reinterpret_cast<const float4*>(
                embed + (size_t)i1 * EMBED_DIM + l * 4);
            const float4 e2 = *reinterpret_cast<const float4*>(
                embed + (size_t)i2 * EMBED_DIM + l * 4);

            float acc00 = 0.f, acc01 = 0.f, acc02 = 0.f, acc03 = 0.f; // (0,1)
            float acc10 = 0.f, acc11 = 0.f, acc12 = 0.f, acc13 = 0.f; // (0,2)
            float acc20 = 0.f, acc21 = 0.f, acc22 = 0.f, acc23 = 0.f; // (1,2)

#define DIM(x0, x1, x2, W)                                   \
            {                                                \
                const float v01 = (x0) * (x1);               \
                const float v02 = (x0) * (x2);               \
                const float v12 = (x1) * (x2);               \
                acc00 = fmaf(v01, (W).x, acc00);             \
                acc01 = fmaf(v01, (W).y, acc01);             \
                acc02 = fmaf(v01, (W).z, acc02);             \
                acc03 = fmaf(v01, (W).w, acc03);             \
                acc10 = fmaf(v02, (W).x, acc10);             \
                acc11 = fmaf(v02, (W).y, acc11);             \
                acc12 = fmaf(v02, (W).z, acc12);             \
                acc13 = fmaf(v02, (W).w, acc13);             \
                acc20 = fmaf(v12, (W).x, acc20);             \
                acc21 = fmaf(v12, (W).y, acc21);             \
                acc22 = fmaf(v12, (W).z, acc22);             \
                acc23 = fmaf(v12, (W).w, acc23);             \
            }

            DIM(e0.x, e1.x, e2.x, w1r[0]);
            DIM(e0.y, e1.y, e2.y, w1r[1]);
            DIM(e0.z, e1.z, e2.z, w1r[2]);
            DIM(e0.w, e1.w, e2.w, w1r[3]);
#undef DIM

            // Butterfly reduction within the 16-lane subgroup.
#define RED(a)                                               \
            a += __shfl_xor_sync(0xffffffffu, a, 1);         \
            a += __shfl_xor_sync(0xffffffffu, a, 2);         \
            a += __shfl_xor_sync(0xffffffffu, a, 4);         \
            a += __shfl_xor_sync(0xffffffffu, a, 8);
            RED(acc00) RED(acc01) RED(acc02) RED(acc03)
            RED(acc10) RED(acc11) RED(acc12) RED(acc13)
            RED(acc20) RED(acc21) RED(acc22) RED(acc23)
#undef RED

            if (l == 0) {
                auto sig = [](float x) {
                    return __fdividef(1.0f, 1.0f + __expf(-x));
                };
                float a0 = b2r, a1 = b2r, a2 = b2r;
                a0 += sig(acc00 + b10) * w20;
                a0 += sig(acc01 + b11) * w21;
                a0 += sig(acc02 + b12) * w22;
                a0 += sig(acc03 + b13) * w23;

                a1 += sig(acc10 + b10) * w20;
                a1 += sig(acc11 + b11) * w21;
                a1 += sig(acc12 + b12) * w22;
                a1 += sig(acc13 + b13) * w23;

                a2 += sig(acc20 + b10) * w20;
                a2 += sig(acc21 + b11) * w21;
                a2 += sig(acc22 + b12) * w22;
                a2 += sig(acc23 + b13) * w23;

                const float o = bpr + a0 * wp0 + a1 * wp1 + a2 * wp2;
                out[g] = sig(o) * 2.0f - 1.0f;
            }
        }
    }
}

extern "C" void kernel_launch(void* const* d_in, const int* in_sizes, int n_in,
                              void* d_out, int out_size)
{
    const int*   group = (const int*)  d_in[0];
    const float* embed = (const float*)d_in[1];
    const float* W1    = (const float*)d_in[2];
    const float* b1    = (const float*)d_in[3];
    const float* W2    = (const float*)d_in[4];
    const float* b2    = (const float*)d_in[5];
    const float* Wp    = (const float*)d_in[6];
    const float* bp    = (const float*)d_in[7];
    float* out = (float*)d_out;

    // 148 SMs * 3 resident blocks; grid-stride amortizes W1 register loads.
    const int blocks  = 444;
    const int threads = 256;
    afm_kernel<<<blocks, threads>>>(group, embed, W1, b1, W2, b2, Wp, bp, out);
}

// round 4
// speedup vs baseline: 1.3623x; 1.3623x over previous
#include <cuda_runtime.h>
#include <cstdint>

#define N_GROUPS 262144
#define EMBED_DIM 64

typedef unsigned long long u64;

__device__ __forceinline__ u64 mulx2(u64 a, u64 b) {
    u64 d; asm("mul.rn.f32x2 %0, %1, %2;" : "=l"(d) : "l"(a), "l"(b)); return d;
}
__device__ __forceinline__ u64 fmax2(u64 a, u64 b, u64 c) {
    u64 d; asm("fma.rn.f32x2 %0, %1, %2, %3;" : "=l"(d) : "l"(a), "l"(b), "l"(c)); return d;
}
__device__ __forceinline__ u64 pack2(float x, float y) {
    u64 d; asm("mov.b64 %0, {%1, %2};" : "=l"(d) : "f"(x), "f"(y)); return d;
}
__device__ __forceinline__ void unpack2(u64 a, float& x, float& y) {
    asm("mov.b64 {%0, %1}, %2;" : "=f"(x), "=f"(y) : "l"(a));
}
__device__ __forceinline__ float sigf(float x) {
    return __fdividef(1.0f, 1.0f + __expf(-x));
}

// 16 lanes per group, 2 groups per warp.
// Lane l covers dims [4l, 4l+4) (one 16B load per embedding row; 16 lanes
// cover the 256B row fully coalesced). Accumulators are f32x2-packed
// (dim-even half, dim-odd half), folded before the cross-lane reduction.
__global__ __launch_bounds__(256, 3)
void afm_kernel(const int*   __restrict__ group,
                const float* __restrict__ embed,
                const float* __restrict__ W1,
                const float* __restrict__ b1,
                const float* __restrict__ W2,
                const float* __restrict__ b2,
                const float* __restrict__ Wp,
                const float* __restrict__ bp,
                float*       __restrict__ out)
{
    const int lane = threadIdx.x & 31;
    const int sub  = lane >> 4;   // which of 2 groups in this warp
    const int l    = lane & 15;   // lane within the 16-lane subgroup

    const int warp_global = (blockIdx.x * blockDim.x + threadIdx.x) >> 5;
    const int nwarps      = (gridDim.x * blockDim.x) >> 5;

    // Per-lane packed W1: w1p[h][f] = (W1[4l+2h][f], W1[4l+2h+1][f]).
    u64 w1p[2][4];
#pragma unroll
    for (int h = 0; h < 2; h++)
#pragma unroll
        for (int f = 0; f < 4; f++)
            w1p[h][f] = pack2(W1[(4 * l + 2 * h) * 4 + f],
                              (float)W1[(4 * l + 2 * h + 1) * 4 + f]);

    // Exchange-reduction leaves acc index k = bitrev4(l) on lane l.
    const int k = ((l & 1) << 3) | ((l & 2) << 1) | ((l & 4) >> 1) | ((l & 8) >> 3);
    const int f = k & 3;        // feature of this lane's accumulator
    // pair p = k >> 2 ; membership of the final quads is by (l & 3):
    //   l&3==0 -> pair 0, l&3==2 -> pair 1, l&3==1 -> pair 2, l&3==3 -> pad
    const float myb1  = (k < 12) ? b1[f] : 0.0f;
    const float myw2  = (k < 12) ? W2[f] : 0.0f;
    const int   q     = l & 3;
    float mywp = 0.0f;
    if (q == 0) mywp = Wp[0];
    else if (q == 2) mywp = Wp[1];
    else if (q == 1) mywp = Wp[2];
    const float mybp = (q == 0) ? bp[0] : 0.0f;
    const float b2r  = b2[0];

    for (int g0 = warp_global * 8; g0 < N_GROUPS; g0 += nwarps * 8) {
        // One coalesced load of 24 indices = 8 groups' worth for this warp.
        int v = 0;
        if (lane < 24) v = group[g0 * 3 + lane];

#pragma unroll
        for (int it = 0; it < 4; it++) {
            const int i0 = __shfl_sync(0xffffffffu, v, it * 6 + sub * 3 + 0);
            const int i1 = __shfl_sync(0xffffffffu, v, it * 6 + sub * 3 + 1);
            const int i2 = __shfl_sync(0xffffffffu, v, it * 6 + sub * 3 + 2);

            const ulonglong2 E0 = *reinterpret_cast<const ulonglong2*>(
                embed + (size_t)i0 * EMBED_DIM + l * 4);
            const ulonglong2 E1 = *reinterpret_cast<const ulonglong2*>(
                embed + (size_t)i1 * EMBED_DIM + l * 4);
            const ulonglong2 E2 = *reinterpret_cast<const ulonglong2*>(
                embed + (size_t)i2 * EMBED_DIM + l * 4);

            u64 acc[12];
#pragma unroll
            for (int i = 0; i < 12; i++) acc[i] = 0ull;

            {
                const u64 v01 = mulx2(E0.x, E1.x);
                const u64 v02 = mulx2(E0.x, E2.x);
                const u64 v12 = mulx2(E1.x, E2.x);
#pragma unroll
                for (int ff = 0; ff < 4; ff++) {
                    acc[ff]     = fmax2(v01, w1p[0][ff], acc[ff]);
                    acc[4 + ff] = fmax2(v02, w1p[0][ff], acc[4 + ff]);
                    acc[8 + ff] = fmax2(v12, w1p[0][ff], acc[8 + ff]);
                }
            }
            {
                const u64 v01 = mulx2(E0.y, E1.y);
                const u64 v02 = mulx2(E0.y, E2.y);
                const u64 v12 = mulx2(E1.y, E2.y);
#pragma unroll
                for (int ff = 0; ff < 4; ff++) {
                    acc[ff]     = fmax2(v01, w1p[1][ff], acc[ff]);
                    acc[4 + ff] = fmax2(v02, w1p[1][ff], acc[4 + ff]);
                    acc[8 + ff] = fmax2(v12, w1p[1][ff], acc[8 + ff]);
                }
            }

            // Fold packed halves -> 12 scalars (+4 zero pads).
            float r[16];
#pragma unroll
            for (int i = 0; i < 12; i++) {
                float x, y;
                unpack2(acc[i], x, y);
                r[i] = x + y;
            }
            r[12] = r[13] = r[14] = r[15] = 0.0f;

            // Exchange reduction: 16 values over 16 lanes in 15 shuffles.
            // After step s, lane keeps the half selected by its lane bit.
            {
                const bool hb = l & 1;
#pragma unroll
                for (int j = 0; j < 8; j++) {
                    const float send = hb ? r[j] : r[j + 8];
                    const float recv = __shfl_xor_sync(0xffffffffu, send, 1);
                    r[j] = (hb ? r[j + 8] : r[j]) + recv;
                }
            }
            {
                const bool hb = l & 2;
#pragma unroll
                for (int j = 0; j < 4; j++) {
                    const float send = hb ? r[j] : r[j + 4];
                    const float recv = __shfl_xor_sync(0xffffffffu, send, 2);
                    r[j] = (hb ? r[j + 4] : r[j]) + recv;
                }
            }
            {
                const bool hb = l & 4;
#pragma unroll
                for (int j = 0; j < 2; j++) {
                    const float send = hb ? r[j] : r[j + 2];
                    const float recv = __shfl_xor_sync(0xffffffffu, send, 4);
                    r[j] = (hb ? r[j + 2] : r[j]) + recv;
                }
            }
            {
                const bool hb = l & 8;
                const float send = hb ? r[0] : r[1];
                const float recv = __shfl_xor_sync(0xffffffffu, send, 8);
                r[0] = (hb ? r[1] : r[0]) + recv;
            }
            const float R = r[0];  // fully-reduced acc for index k = bitrev4(l)

            // Distributed epilogue: one sigmoid per lane.
            float t = sigf(R + myb1) * myw2;
            // Sum the 4 features of each pair (lanes {x, x+4, x+8, x+12}).
            t += __shfl_xor_sync(0xffffffffu, t, 4);
            t += __shfl_xor_sync(0xffffffffu, t, 8);
            // z = a_p * Wp_p (+ bp once per quad); pads have mywp = 0.
            float z = fmaf(t + b2r, mywp, mybp);
            z += __shfl_xor_sync(0xffffffffu, z, 1);
            z += __shfl_xor_sync(0xffffffffu, z, 2);

            if (l == 0)
                out[g0 + it * 2 + sub] = sigf(z) * 2.0f - 1.0f;
        }
    }
}

extern "C" void kernel_launch(void* const* d_in, const int* in_sizes, int n_in,
                              void* d_out, int out_size)
{
    const int*   group = (const int*)  d_in[0];
    const float* embed = (const float*)d_in[1];
    const float* W1    = (const float*)d_in[2];
    const float* b1    = (const float*)d_in[3];
    const float* W2    = (const float*)d_in[4];
    const float* b2    = (const float*)d_in[5];
    const float* Wp    = (const float*)d_in[6];
    const float* bp    = (const float*)d_in[7];
    float* out = (float*)d_out;

    const int blocks  = 444;   // 148 SMs * 3 resident blocks
    const int threads = 256;
    afm_kernel<<<blocks, threads>>>(group, embed, W1, b1, W2, b2, Wp, bp, out);
}

// round 5
// speedup vs baseline: 1.5468x; 1.1354x over previous
#include <cuda_runtime.h>
#include <cstdint>

#define N_GROUPS 262144
#define EMBED_DIM 64

typedef unsigned long long u64;

__device__ __forceinline__ u64 mulx2(u64 a, u64 b) {
    u64 d; asm("mul.rn.f32x2 %0, %1, %2;" : "=l"(d) : "l"(a), "l"(b)); return d;
}
__device__ __forceinline__ u64 fmax2(u64 a, u64 b, u64 c) {
    u64 d; asm("fma.rn.f32x2 %0, %1, %2, %3;" : "=l"(d) : "l"(a), "l"(b), "l"(c)); return d;
}
__device__ __forceinline__ u64 pack2(float x, float y) {
    u64 d; asm("mov.b64 %0, {%1, %2};" : "=l"(d) : "f"(x), "f"(y)); return d;
}
__device__ __forceinline__ void unpack2(u64 a, float& x, float& y) {
    asm("mov.b64 {%0, %1}, %2;" : "=f"(x), "=f"(y) : "l"(a));
}
__device__ __forceinline__ float sigf(float x) {
    return __fdividef(1.0f, 1.0f + __expf(-x));
}

// 8 lanes per group, 4 groups per warp.
// Lane l3 covers dims {4*l3..4*l3+3, 32+4*l3..32+4*l3+3} via two float4 loads
// per embedding row (8 lanes x 16B x 2 = fully coalesced 256B row).
// The 14-shfl exchange reduction (masks 1,2,4) serves all 4 groups at once.
__global__ __launch_bounds__(128, 5)
void afm_kernel(const int*   __restrict__ group,
                const float* __restrict__ embed,
                const float* __restrict__ W1,
                const float* __restrict__ b1,
                const float* __restrict__ W2,
                const float* __restrict__ b2,
                const float* __restrict__ Wp,
                const float* __restrict__ bp,
                float*       __restrict__ out)
{
    const int lane = threadIdx.x & 31;
    const int sub  = lane >> 3;   // which of 4 groups in this warp
    const int l3   = lane & 7;    // lane within the 8-lane subgroup

    const int warp_global = (blockIdx.x * blockDim.x + threadIdx.x) >> 5;
    const int nwarps      = (gridDim.x * blockDim.x) >> 5;

    // Per-lane packed W1: dim-pairs (4*l3+2h, 4*l3+2h+1) and (32+4*l3+2h, +1).
    u64 w1p[4][4];
#pragma unroll
    for (int dp = 0; dp < 4; dp++) {
        const int d0 = (dp < 2) ? (4 * l3 + 2 * dp) : (32 + 4 * l3 + 2 * (dp - 2));
#pragma unroll
        for (int f = 0; f < 4; f++)
            w1p[dp][f] = pack2(W1[d0 * 4 + f], W1[(d0 + 1) * 4 + f]);
    }

    // Exchange leaves acc indices k0 = 2*bitrev3(l3), k1 = k0+1 on lane l3.
    const int br = ((l3 & 1) << 2) | (l3 & 2) | ((l3 & 4) >> 2);
    const int k0 = 2 * br, k1 = k0 + 1;
    const float b1a = (k0 < 12) ? b1[k0 & 3] : 0.0f;
    const float b1b = (k1 < 12) ? b1[k1 & 3] : 0.0f;
    const float w2a = (k0 < 12) ? W2[k0 & 3] : 0.0f;
    const float w2b = (k1 < 12) ? W2[k1 & 3] : 0.0f;
    // After the +4 pair-sum: a_0 on lanes {0,4}, a_1 on {2,6}, a_2 on {1,5}.
    const int   q    = l3 & 3;
    float mywp = 0.0f;
    if (q == 0) mywp = Wp[0];
    else if (q == 2) mywp = Wp[1];
    else if (q == 1) mywp = Wp[2];
    const float mybp = (q == 0) ? bp[0] : 0.0f;
    const float b2r  = b2[0];

    for (int g0 = warp_global * 8; g0 < N_GROUPS; g0 += nwarps * 8) {
        // One coalesced load of 24 indices = 8 groups (2 inner iterations).
        int v = 0;
        if (lane < 24 && g0 * 3 + lane < N_GROUPS * 3)
            v = group[g0 * 3 + lane];

#pragma unroll
        for (int it = 0; it < 2; it++) {
            const int g  = g0 + it * 4 + sub;
            const int i0 = __shfl_sync(0xffffffffu, v, it * 12 + sub * 3 + 0);
            const int i1 = __shfl_sync(0xffffffffu, v, it * 12 + sub * 3 + 1);
            const int i2 = __shfl_sync(0xffffffffu, v, it * 12 + sub * 3 + 2);

            const float* p0 = embed + (size_t)i0 * EMBED_DIM + l3 * 4;
            const float* p1 = embed + (size_t)i1 * EMBED_DIM + l3 * 4;
            const float* p2 = embed + (size_t)i2 * EMBED_DIM + l3 * 4;

            const ulonglong2 E0a = *reinterpret_cast<const ulonglong2*>(p0);
            const ulonglong2 E1a = *reinterpret_cast<const ulonglong2*>(p1);
            const ulonglong2 E2a = *reinterpret_cast<const ulonglong2*>(p2);
            const ulonglong2 E0b = *reinterpret_cast<const ulonglong2*>(p0 + 32);
            const ulonglong2 E1b = *reinterpret_cast<const ulonglong2*>(p1 + 32);
            const ulonglong2 E2b = *reinterpret_cast<const ulonglong2*>(p2 + 32);

            u64 acc[12];
#pragma unroll
            for (int i = 0; i < 12; i++) acc[i] = 0ull;

#define DP(e0, e1, e2, dp)                                       \
            {                                                    \
                const u64 v01 = mulx2(e0, e1);                   \
                const u64 v02 = mulx2(e0, e2);                   \
                const u64 v12 = mulx2(e1, e2);                   \
                _Pragma("unroll")                                \
                for (int ff = 0; ff < 4; ff++) {                 \
                    acc[ff]     = fmax2(v01, w1p[dp][ff], acc[ff]);      \
                    acc[4 + ff] = fmax2(v02, w1p[dp][ff], acc[4 + ff]);  \
                    acc[8 + ff] = fmax2(v12, w1p[dp][ff], acc[8 + ff]);  \
                }                                                \
            }
            DP(E0a.x, E1a.x, E2a.x, 0)
            DP(E0a.y, E1a.y, E2a.y, 1)
            DP(E0b.x, E1b.x, E2b.x, 2)
            DP(E0b.y, E1b.y, E2b.y, 3)
#undef DP

            // Fold packed halves -> 12 scalars (+4 zero pads).
            float r[16];
#pragma unroll
            for (int i = 0; i < 12; i++) {
                float x, y;
                unpack2(acc[i], x, y);
                r[i] = x + y;
            }
            r[12] = r[13] = r[14] = r[15] = 0.0f;

            // Exchange reduction over the 8-lane subgroup: 16 values,
            // 14 shuffles (masks 1, 2, 4). Serves all 4 groups at once.
            {
                const bool hb = l3 & 1;
#pragma unroll
                for (int j = 0; j < 8; j++) {
                    const float send = hb ? r[j] : r[j + 8];
                    const float recv = __shfl_xor_sync(0xffffffffu, send, 1);
                    r[j] = (hb ? r[j + 8] : r[j]) + recv;
                }
            }
            {
                const bool hb = l3 & 2;
#pragma unroll
                for (int j = 0; j < 4; j++) {
                    const float send = hb ? r[j] : r[j + 4];
                    const float recv = __shfl_xor_sync(0xffffffffu, send, 2);
                    r[j] = (hb ? r[j + 4] : r[j]) + recv;
                }
            }
            {
                const bool hb = l3 & 4;
#pragma unroll
                for (int j = 0; j < 2; j++) {
                    const float send = hb ? r[j] : r[j + 2];
                    const float recv = __shfl_xor_sync(0xffffffffu, send, 4);
                    r[j] = (hb ? r[j + 2] : r[j]) + recv;
                }
            }
            // Lane l3 now holds fully-reduced accs k0 = 2*bitrev3(l3), k0+1.

            // Distributed epilogue: two sigmoids per lane serve 4 groups.
            float t = sigf(r[0] + b1a) * w2a + sigf(r[1] + b1b) * w2b;
            // Sum each pair's 4 features (lane pairs differing in bit 2).
            t += __shfl_xor_sync(0xffffffffu, t, 4);
            // z = a_p * Wp_p (+ bp on q==0); pads contribute 0 via mywp=0.
            float z = fmaf(t + b2r, mywp, mybp);
            z += __shfl_xor_sync(0xffffffffu, z, 1);
            z += __shfl_xor_sync(0xffffffffu, z, 2);

            if (l3 == 0 && g < N_GROUPS)
                out[g] = sigf(z) * 2.0f - 1.0f;
        }
    }
}

extern "C" void kernel_launch(void* const* d_in, const int* in_sizes, int n_in,
                              void* d_out, int out_size)
{
    const int*   group = (const int*)  d_in[0];
    const float* embed = (const float*)d_in[1];
    const float* W1    = (const float*)d_in[2];
    const float* b1    = (const float*)d_in[3];
    const float* W2    = (const float*)d_in[4];
    const float* b2    = (const float*)d_in[5];
    const float* Wp    = (const float*)d_in[6];
    const float* bp    = (const float*)d_in[7];
    float* out = (float*)d_out;

    const int blocks  = 740;   // 148 SMs * 5 resident blocks of 128 threads
    const int threads = 128;
    afm_kernel<<<blocks, threads>>>(group, embed, W1, b1, W2, b2, Wp, bp, out);
}

// round 6
// speedup vs baseline: 1.5764x; 1.0191x over previous
#include <cuda_runtime.h>
#include <cstdint>

#define N_GROUPS 262144
#define EMBED_DIM 64

typedef unsigned long long u64;

__device__ __forceinline__ u64 mulx2(u64 a, u64 b) {
    u64 d; asm("mul.rn.f32x2 %0, %1, %2;" : "=l"(d) : "l"(a), "l"(b)); return d;
}
__device__ __forceinline__ u64 fmax2(u64 a, u64 b, u64 c) {
    u64 d; asm("fma.rn.f32x2 %0, %1, %2, %3;" : "=l"(d) : "l"(a), "l"(b), "l"(c)); return d;
}
__device__ __forceinline__ u64 pack2(float x, float y) {
    u64 d; asm("mov.b64 %0, {%1, %2};" : "=l"(d) : "f"(x), "f"(y)); return d;
}
__device__ __forceinline__ void unpack2(u64 a, float& x, float& y) {
    asm("mov.b64 {%0, %1}, %2;" : "=f"(x), "=f"(y) : "l"(a));
}
__device__ __forceinline__ float sigf(float x) {
    return __fdividef(1.0f, 1.0f + __expf(-x));
}

// 8 lanes per group, 4 groups per warp.
// Lane l3 covers dims {4*l3..4*l3+3, 32+4*l3..32+4*l3+3} via two float4 loads
// per embedding row. W1 slices live in padded smem (conflict-free LDS.128),
// freeing 32 registers -> 28 warps/SM for gather-latency cover.
__global__ __launch_bounds__(128, 7)
void afm_kernel(const int*   __restrict__ group,
                const float* __restrict__ embed,
                const float* __restrict__ W1,
                const float* __restrict__ b1,
                const float* __restrict__ W2,
                const float* __restrict__ b2,
                const float* __restrict__ Wp,
                const float* __restrict__ bp,
                float*       __restrict__ out)
{
    // Packed W1 slices: smw[l3][dp*4+f] = (W1[d0][f], W1[d0+1][f]).
    // Row stride 18 u64 = 144 B: lane l3 -> banks 4*l3..4*l3+3 (conflict-free,
    // 4-way broadcast across the 4 subgroups).
    __shared__ u64 smw[8][18];
    {
        const int t = threadIdx.x;           // blockDim.x == 128
        const int l  = t >> 4;
        const int idx = t & 15;
        const int dp = idx >> 2, f = idx & 3;
        const int d0 = (dp < 2) ? (4 * l + 2 * dp) : (32 + 4 * l + 2 * (dp - 2));
        smw[l][dp * 4 + f] = pack2(W1[d0 * 4 + f], W1[(d0 + 1) * 4 + f]);
    }
    __syncthreads();

    const int lane = threadIdx.x & 31;
    const int sub  = lane >> 3;   // which of 4 groups in this warp
    const int l3   = lane & 7;    // lane within the 8-lane subgroup

    const int warp_global = (blockIdx.x * blockDim.x + threadIdx.x) >> 5;
    const int nwarps      = (gridDim.x * blockDim.x) >> 5;

    // Exchange leaves acc indices k0 = 2*bitrev3(l3), k1 = k0+1 on lane l3.
    const int br = ((l3 & 1) << 2) | (l3 & 2) | ((l3 & 4) >> 2);
    const int k0 = 2 * br, k1 = k0 + 1;
    const float b1a = (k0 < 12) ? b1[k0 & 3] : 0.0f;
    const float b1b = (k1 < 12) ? b1[k1 & 3] : 0.0f;
    const float w2a = (k0 < 12) ? W2[k0 & 3] : 0.0f;
    const float w2b = (k1 < 12) ? W2[k1 & 3] : 0.0f;
    // After the +4 pair-sum: a_0 on lanes {0,4}, a_1 on {2,6}, a_2 on {1,5}.
    const int q = l3 & 3;
    float mywp = 0.0f;
    if (q == 0) mywp = Wp[0];
    else if (q == 2) mywp = Wp[1];
    else if (q == 1) mywp = Wp[2];
    const float mybp = (q == 0) ? bp[0] : 0.0f;
    const float b2r  = b2[0];

    for (int g0 = warp_global * 8; g0 < N_GROUPS; g0 += nwarps * 8) {
        // One coalesced load of 24 indices = 8 groups (2 inner iterations).
        int v = 0;
        if (lane < 24) v = group[g0 * 3 + lane];

#pragma unroll
        for (int it = 0; it < 2; it++) {
            const int g  = g0 + it * 4 + sub;
            const int i0 = __shfl_sync(0xffffffffu, v, it * 12 + sub * 3 + 0);
            const int i1 = __shfl_sync(0xffffffffu, v, it * 12 + sub * 3 + 1);
            const int i2 = __shfl_sync(0xffffffffu, v, it * 12 + sub * 3 + 2);

            const float* p0 = embed + (size_t)i0 * EMBED_DIM + l3 * 4;
            const float* p1 = embed + (size_t)i1 * EMBED_DIM + l3 * 4;
            const float* p2 = embed + (size_t)i2 * EMBED_DIM + l3 * 4;

            const ulonglong2 E0a = *reinterpret_cast<const ulonglong2*>(p0);
            const ulonglong2 E1a = *reinterpret_cast<const ulonglong2*>(p1);
            const ulonglong2 E2a = *reinterpret_cast<const ulonglong2*>(p2);
            const ulonglong2 E0b = *reinterpret_cast<const ulonglong2*>(p0 + 32);
            const ulonglong2 E1b = *reinterpret_cast<const ulonglong2*>(p1 + 32);
            const ulonglong2 E2b = *reinterpret_cast<const ulonglong2*>(p2 + 32);

            u64 acc[12];
#pragma unroll
            for (int i = 0; i < 12; i++) acc[i] = 0ull;

#define DP(e0, e1, e2, dp)                                                  \
            {                                                               \
                const ulonglong2 wlo = *reinterpret_cast<const ulonglong2*>(\
                    &smw[l3][(dp) * 4 + 0]);                                \
                const ulonglong2 whi = *reinterpret_cast<const ulonglong2*>(\
                    &smw[l3][(dp) * 4 + 2]);                                \
                const u64 v01 = mulx2(e0, e1);                              \
                const u64 v02 = mulx2(e0, e2);                              \
                const u64 v12 = mulx2(e1, e2);                              \
                acc[0]  = fmax2(v01, wlo.x, acc[0]);                        \
                acc[1]  = fmax2(v01, wlo.y, acc[1]);                        \
                acc[2]  = fmax2(v01, whi.x, acc[2]);                        \
                acc[3]  = fmax2(v01, whi.y, acc[3]);                        \
                acc[4]  = fmax2(v02, wlo.x, acc[4]);                        \
                acc[5]  = fmax2(v02, wlo.y, acc[5]);                        \
                acc[6]  = fmax2(v02, whi.x, acc[6]);                        \
                acc[7]  = fmax2(v02, whi.y, acc[7]);                        \
                acc[8]  = fmax2(v12, wlo.x, acc[8]);                        \
                acc[9]  = fmax2(v12, wlo.y, acc[9]);                        \
                acc[10] = fmax2(v12, whi.x, acc[10]);                       \
                acc[11] = fmax2(v12, whi.y, acc[11]);                       \
            }
            DP(E0a.x, E1a.x, E2a.x, 0)
            DP(E0a.y, E1a.y, E2a.y, 1)
            DP(E0b.x, E1b.x, E2b.x, 2)
            DP(E0b.y, E1b.y, E2b.y, 3)
#undef DP

            // Fold packed halves -> 12 scalars (+4 zero pads).
            float r[16];
#pragma unroll
            for (int i = 0; i < 12; i++) {
                float x, y;
                unpack2(acc[i], x, y);
                r[i] = x + y;
            }
            r[12] = r[13] = r[14] = r[15] = 0.0f;

            // Exchange reduction over the 8-lane subgroup: 16 values,
            // 14 shuffles (masks 1, 2, 4). Serves all 4 groups at once.
            {
                const bool hb = l3 & 1;
#pragma unroll
                for (int j = 0; j < 8; j++) {
                    const float send = hb ? r[j] : r[j + 8];
                    const float recv = __shfl_xor_sync(0xffffffffu, send, 1);
                    r[j] = (hb ? r[j + 8] : r[j]) + recv;
                }
            }
            {
                const bool hb = l3 & 2;
#pragma unroll
                for (int j = 0; j < 4; j++) {
                    const float send = hb ? r[j] : r[j + 4];
                    const float recv = __shfl_xor_sync(0xffffffffu, send, 2);
                    r[j] = (hb ? r[j + 4] : r[j]) + recv;
                }
            }
            {
                const bool hb = l3 & 4;
#pragma unroll
                for (int j = 0; j < 2; j++) {
                    const float send = hb ? r[j] : r[j + 2];
                    const float recv = __shfl_xor_sync(0xffffffffu, send, 4);
                    r[j] = (hb ? r[j + 2] : r[j]) + recv;
                }
            }
            // Lane l3 now holds fully-reduced accs k0 = 2*bitrev3(l3), k0+1.

            // Distributed epilogue: two sigmoids per lane serve 4 groups.
            float t = sigf(r[0] + b1a) * w2a + sigf(r[1] + b1b) * w2b;
            t += __shfl_xor_sync(0xffffffffu, t, 4);
            float z = fmaf(t + b2r, mywp, mybp);
            z += __shfl_xor_sync(0xffffffffu, z, 1);
            z += __shfl_xor_sync(0xffffffffu, z, 2);

            if (l3 == 0)
                out[g] = sigf(z) * 2.0f - 1.0f;
        }
    }
}

extern "C" void kernel_launch(void* const* d_in, const int* in_sizes, int n_in,
                              void* d_out, int out_size)
{
    const int*   group = (const int*)  d_in[0];
    const float* embed = (const float*)d_in[1];
    const float* W1    = (const float*)d_in[2];
    const float* b1    = (const float*)d_in[3];
    const float* W2    = (const float*)d_in[4];
    const float* b2    = (const float*)d_in[5];
    const float* Wp    = (const float*)d_in[6];
    const float* bp    = (const float*)d_in[7];
    float* out = (float*)d_out;

    const int blocks  = 1036;  // 148 SMs * 7 resident blocks of 128 threads
    const int threads = 128;
    afm_kernel<<<blocks, threads>>>(group, embed, W1, b1, W2, b2, Wp, bp, out);
}